// round 9
// baseline (speedup 1.0000x reference)
#include <cuda_runtime.h>
#include <cstdint>

#define NB 512
#define NT 2048
#define NK 8
#define ND 32
#define DTC 0.05f
#define SQDT 0.22360679774997896f  // sqrt(0.05)
#define PF 6                        // prefetch distance (steps)
#define RING 8                      // smem ring slots

typedef unsigned long long ull;

__device__ __forceinline__ ull ffma2(ull a, ull b, ull c) {
    ull d;
    asm("fma.rn.f32x2 %0, %1, %2, %3;" : "=l"(d) : "l"(a), "l"(b), "l"(c));
    return d;
}
__device__ __forceinline__ float2 unpack2(ull v) {
    float2 r;
    asm("mov.b64 {%0, %1}, %2;" : "=f"(r.x), "=f"(r.y) : "l"(v));
    return r;
}
__device__ __forceinline__ ull pack2(float lo, float hi) {
    ull v;
    asm("mov.b64 %0, {%1, %2};" : "=l"(v) : "f"(lo), "f"(hi));
    return v;
}
__device__ __forceinline__ void cp16(uint32_t saddr, const void* gaddr) {
    asm volatile("cp.async.ca.shared.global [%0], [%1], 16;"
                 :: "r"(saddr), "l"(gaddr) : "memory");
}

__global__ void __launch_bounds__(64, 1)
slds_scan_kernel(const float* __restrict__ z0,
                 const float* __restrict__ s_probs,  // [T,B,K]
                 const float* __restrict__ noise,    // [T,B,D]
                 const float* __restrict__ A_s,      // [K,D,D]
                 const float* __restrict__ b_s,      // [K,D]
                 const float* __restrict__ Q_chol,   // [K,D]
                 float* __restrict__ ys)             // [T,B,D]
{
    __shared__ __align__(16) float sm_w[RING][8];
    __shared__ __align__(16) float sm_n[RING][ND];
    __shared__ __align__(16) float sm_z[2][ND];      // double-buffered state

    const int l  = threadIdx.x & 31;   // lane
    const int h  = threadIdx.x >> 5;   // warp: dims [16h, 16h+16)
    const int i  = 16 * h + (l >> 1);  // owned output dim
    const int jh = l & 1;              // j-half: columns [16jh, 16jh+16)
    const int b  = blockIdx.x;

    const ull ONE2 = pack2(1.0f, 1.0f);

    // ---- A rows (all 8 k, this lane's j-half) as 8 f32x2 pairs each ----
    ull A2[NK][8];
#pragma unroll
    for (int k = 0; k < NK; k++) {
        const ulonglong2* row = reinterpret_cast<const ulonglong2*>(
            A_s + ((size_t)k * ND + i) * ND + 16 * jh);
#pragma unroll
        for (int m = 0; m < 4; m++) {
            ulonglong2 v = row[m];
            A2[k][2 * m + 0] = v.x;
            A2[k][2 * m + 1] = v.y;
        }
    }
    // identity mask: 1.0 in the packed slot holding column j == i (if owned)
    ull dmask8[8];
#pragma unroll
    for (int p = 0; p < 8; p++) {
        const bool owned = ((i >> 4) == jh) && (((i & 15) >> 1) == p);
        dmask8[p] = owned ? pack2((i & 1) == 0 ? 1.0f : 0.0f,
                                  (i & 1) == 1 ? 1.0f : 0.0f)
                          : 0ull;
    }
    // c-vector: even lanes carry drift bias, odd lanes carry diffusion diag
    float cvec[NK];
#pragma unroll
    for (int k = 0; k < NK; k++)
        cvec[k] = (jh == 0) ? b_s[k * ND + i] : Q_chol[k * ND + i];

    // ---- cp.async ring (warp 0 issues) ----
    const uint32_t s_n = (uint32_t)__cvta_generic_to_shared(&sm_n[0][0]);
    const uint32_t s_w = (uint32_t)__cvta_generic_to_shared(&sm_w[0][0]);
    const float* gn = noise   + (size_t)b * ND;
    const float* gw = s_probs + (size_t)b * NK;

    if (h == 0) {
#pragma unroll
        for (int s = 0; s < PF; s++) {
            if (l < 8)
                cp16(s_n + (uint32_t)(s * ND + l * 4) * 4,
                     gn + (size_t)s * NB * ND + l * 4);
            else if (l < 10)
                cp16(s_w + (uint32_t)(s * 8 + (l - 8) * 4) * 4,
                     gw + (size_t)s * NB * NK + (l - 8) * 4);
            asm volatile("cp.async.commit_group;" ::: "memory");
        }
        // guarantee slots 0 AND 1 complete (we read slot t+1 during step t)
        asm volatile("cp.async.wait_group %0;" :: "n"(PF - 2) : "memory");
    }

    // ---- initial state into buffer 0 ----
    if (jh == 0) sm_z[0][i] = z0[(size_t)b * ND + i];
    __syncthreads();   // publishes ring slots 0..1 + sm_z[0]

    float* yp = ys + (size_t)b * ND + i;

    // build M_slot/c_slot from ring slot S (off-chain work)
#define BUILD(S, M, C) do {                                                   \
        const float4 wa_ = *reinterpret_cast<const float4*>(&sm_w[(S)][0]);   \
        const float4 wb_ = *reinterpret_cast<const float4*>(&sm_w[(S)][4]);   \
        const float wsum_ = ((wa_.x + wa_.y) + (wa_.z + wa_.w)) +             \
                            ((wb_.x + wb_.y) + (wb_.z + wb_.w));              \
        const float inv_ = __fdividef(1.0f, wsum_);                           \
        const float dti_ = DTC * inv_;                                        \
        const float wsc_[8] = { wa_.x, wa_.y, wa_.z, wa_.w,                   \
                                wb_.x, wb_.y, wb_.z, wb_.w };                 \
        ull wt_[8];                                                           \
        _Pragma("unroll")                                                     \
        for (int k = 0; k < 8; k++) {                                         \
            const float s_ = dti_ * wsc_[k];                                  \
            wt_[k] = pack2(s_, s_);                                           \
        }                                                                     \
        _Pragma("unroll")                                                     \
        for (int p = 0; p < 8; p++) {                                         \
            ull a_ = dmask8[p];                                               \
            _Pragma("unroll")                                                 \
            for (int k = 0; k < 8; k++) a_ = ffma2(wt_[k], A2[k][p], a_);     \
            (M)[p] = a_;                                                      \
        }                                                                     \
        float acc_ = 0.0f;                                                    \
        _Pragma("unroll")                                                     \
        for (int k = 0; k < 8; k++) acc_ = fmaf(wsc_[k], cvec[k], acc_);      \
        const float n1_ = sm_n[(S)][i];                                       \
        (C) = acc_ * (jh ? inv_ * SQDT * n1_ : dti_);                         \
    } while (0)

    // one full step: chain matvec with (MC, CC), build (MN, CN) for t+1
#define STEP(T, RB, WB, MC, CC, MN, CN) do {                                  \
        /* ---- z-critical chain ---- */                                      \
        const ulonglong2* zsrc_ =                                             \
            reinterpret_cast<const ulonglong2*>(&sm_z[(RB)][16 * jh]);        \
        ulonglong2 z4_[4];                                                    \
        _Pragma("unroll")                                                     \
        for (int m = 0; m < 4; m++) z4_[m] = zsrc_[m];                        \
        ull ae_ = pack2((CC), 0.0f), ao_ = 0ull;                              \
        _Pragma("unroll")                                                     \
        for (int m = 0; m < 4; m++) {                                         \
            ae_ = ffma2((MC)[2 * m + 0], z4_[m].x, ae_);                      \
            ao_ = ffma2((MC)[2 * m + 1], z4_[m].y, ao_);                      \
        }                                                                     \
        const float2 sv_ = unpack2(ffma2(ae_, ONE2, ao_));                    \
        const float ph_ = sv_.x + sv_.y;                                      \
        const float zi_ = ph_ + __shfl_xor_sync(0xffffffffu, ph_, 1);         \
        /* ---- off-chain: prefetch + next-step M/c ---- */                   \
        if (h == 0) {                                                         \
            const int tp_ = (T) + PF;                                         \
            if (tp_ < NT) {                                                   \
                const int ps_ = tp_ & (RING - 1);                             \
                if (l < 8)                                                    \
                    cp16(s_n + (uint32_t)(ps_ * ND + l * 4) * 4,              \
                         gn + (size_t)tp_ * NB * ND + l * 4);                 \
                else if (l < 10)                                              \
                    cp16(s_w + (uint32_t)(ps_ * 8 + (l - 8) * 4) * 4,         \
                         gw + (size_t)tp_ * NB * NK + (l - 8) * 4);           \
            }                                                                 \
            asm volatile("cp.async.commit_group;" ::: "memory");              \
        }                                                                     \
        BUILD(((T) + 1) & (RING - 1), (MN), (CN));                            \
        /* ---- publish ---- */                                               \
        if (jh == 0) {                                                        \
            sm_z[(WB)][i] = zi_;                                              \
            yp[(size_t)(T) * NB * ND] = zi_;                                  \
        }                                                                     \
        if (h == 0)                                                           \
            asm volatile("cp.async.wait_group %0;" :: "n"(PF - 2) : "memory");\
        __syncthreads();                                                      \
    } while (0)

    // prologue: M/c for step 0 from ring slot 0
    ull Mc[8], Mn[8];
    float cC, cN;
    BUILD(0, Mc, cC);

    for (int t = 0; t < NT; t += 2) {
        STEP(t,     0, 1, Mc, cC, Mn, cN);
        STEP(t + 1, 1, 0, Mn, cN, Mc, cC);
    }
#undef STEP
#undef BUILD
}

extern "C" void kernel_launch(void* const* d_in, const int* in_sizes, int n_in,
                              void* d_out, int out_size) {
    const float* z0      = (const float*)d_in[0];
    const float* s_probs = (const float*)d_in[1];
    const float* noise   = (const float*)d_in[2];
    const float* A_s     = (const float*)d_in[3];
    const float* b_s     = (const float*)d_in[4];
    const float* Q_chol  = (const float*)d_in[5];
    float* ys = (float*)d_out;

    slds_scan_kernel<<<NB, 64>>>(z0, s_probs, noise, A_s, b_s, Q_chol, ys);
}

// round 10
// speedup vs baseline: 1.0007x; 1.0007x over previous
#include <cuda_runtime.h>
#include <cstdint>

#define NB 512
#define NT 2048
#define NK 8
#define ND 32
#define DTC 0.05f
#define SQDT 0.22360679774997896f  // sqrt(0.05)
#define PF 6                        // prefetch distance (steps)
#define RING 8                      // smem ring slots

typedef unsigned long long ull;

__device__ __forceinline__ ull ffma2(ull a, ull b, ull c) {
    ull d;
    asm("fma.rn.f32x2 %0, %1, %2, %3;" : "=l"(d) : "l"(a), "l"(b), "l"(c));
    return d;
}
__device__ __forceinline__ float2 unpack2(ull v) {
    float2 r;
    asm("mov.b64 {%0, %1}, %2;" : "=f"(r.x), "=f"(r.y) : "l"(v));
    return r;
}
__device__ __forceinline__ ull pack2(float lo, float hi) {
    ull v;
    asm("mov.b64 %0, {%1, %2};" : "=l"(v) : "f"(lo), "f"(hi));
    return v;
}
__device__ __forceinline__ void cp16(uint32_t saddr, const void* gaddr) {
    asm volatile("cp.async.ca.shared.global [%0], [%1], 16;"
                 :: "r"(saddr), "l"(gaddr) : "memory");
}

__global__ void __launch_bounds__(64, 1)
slds_scan_kernel(const float* __restrict__ z0,
                 const float* __restrict__ s_probs,  // [T,B,K]
                 const float* __restrict__ noise,    // [T,B,D]
                 const float* __restrict__ A_s,      // [K,D,D]
                 const float* __restrict__ b_s,      // [K,D]
                 const float* __restrict__ Q_chol,   // [K,D]
                 float* __restrict__ ys)             // [T,B,D]
{
    __shared__ __align__(16) float sm_w[RING][8];
    __shared__ __align__(16) float sm_n[RING][ND];
    __shared__ __align__(16) float sm_z[2][ND];      // double-buffered state

    const int l  = threadIdx.x & 31;   // lane
    const int h  = threadIdx.x >> 5;   // warp: dims [16h, 16h+16)
    const int i  = 16 * h + (l >> 1);  // owned output dim
    const int jh = l & 1;              // j-half: columns [16jh, 16jh+16)
    const int b  = blockIdx.x;

    const ull ONE2 = pack2(1.0f, 1.0f);

    // ---- A rows (all 8 k, this lane's j-half) as 8 f32x2 pairs each ----
    ull A2[NK][8];
#pragma unroll
    for (int k = 0; k < NK; k++) {
        const ulonglong2* row = reinterpret_cast<const ulonglong2*>(
            A_s + ((size_t)k * ND + i) * ND + 16 * jh);
#pragma unroll
        for (int m = 0; m < 4; m++) {
            ulonglong2 v = row[m];
            A2[k][2 * m + 0] = v.x;
            A2[k][2 * m + 1] = v.y;
        }
    }
    // identity mask: 1.0 in the packed slot holding column j == i (if owned)
    ull dmask8[8];
#pragma unroll
    for (int p = 0; p < 8; p++) {
        const bool owned = ((i >> 4) == jh) && (((i & 15) >> 1) == p);
        dmask8[p] = owned ? pack2((i & 1) == 0 ? 1.0f : 0.0f,
                                  (i & 1) == 1 ? 1.0f : 0.0f)
                          : 0ull;
    }
    // c-vector: even lanes carry drift bias, odd lanes carry diffusion diag
    float cvec[NK];
#pragma unroll
    for (int k = 0; k < NK; k++)
        cvec[k] = (jh == 0) ? b_s[k * ND + i] : Q_chol[k * ND + i];

    // ---- cp.async ring (warp 0 issues) ----
    const uint32_t s_n = (uint32_t)__cvta_generic_to_shared(&sm_n[0][0]);
    const uint32_t s_w = (uint32_t)__cvta_generic_to_shared(&sm_w[0][0]);
    const float* gn = noise   + (size_t)b * ND;
    const float* gw = s_probs + (size_t)b * NK;

    if (h == 0) {
#pragma unroll
        for (int s = 0; s < PF; s++) {
            if (l < 8)
                cp16(s_n + (uint32_t)(s * ND + l * 4) * 4,
                     gn + (size_t)s * NB * ND + l * 4);
            else if (l < 10)
                cp16(s_w + (uint32_t)(s * 8 + (l - 8) * 4) * 4,
                     gw + (size_t)s * NB * NK + (l - 8) * 4);
            asm volatile("cp.async.commit_group;" ::: "memory");
        }
        // guarantee slots 0 AND 1 complete (we read slot t+1 during step t)
        asm volatile("cp.async.wait_group %0;" :: "n"(PF - 2) : "memory");
    }

    // ---- initial state into buffer 0 ----
    if (jh == 0) sm_z[0][i] = z0[(size_t)b * ND + i];
    __syncthreads();   // publishes ring slots 0..1 + sm_z[0]

    float* yp = ys + (size_t)b * ND + i;

    // build M_slot/c_slot from ring slot S (off-chain work)
#define BUILD(S, M, C) do {                                                   \
        const float4 wa_ = *reinterpret_cast<const float4*>(&sm_w[(S)][0]);   \
        const float4 wb_ = *reinterpret_cast<const float4*>(&sm_w[(S)][4]);   \
        const float wsum_ = ((wa_.x + wa_.y) + (wa_.z + wa_.w)) +             \
                            ((wb_.x + wb_.y) + (wb_.z + wb_.w));              \
        const float inv_ = __fdividef(1.0f, wsum_);                           \
        const float dti_ = DTC * inv_;                                        \
        const float wsc_[8] = { wa_.x, wa_.y, wa_.z, wa_.w,                   \
                                wb_.x, wb_.y, wb_.z, wb_.w };                 \
        ull wt_[8];                                                           \
        _Pragma("unroll")                                                     \
        for (int k = 0; k < 8; k++) {                                         \
            const float s_ = dti_ * wsc_[k];                                  \
            wt_[k] = pack2(s_, s_);                                           \
        }                                                                     \
        _Pragma("unroll")                                                     \
        for (int p = 0; p < 8; p++) {                                         \
            ull a_ = dmask8[p];                                               \
            _Pragma("unroll")                                                 \
            for (int k = 0; k < 8; k++) a_ = ffma2(wt_[k], A2[k][p], a_);     \
            (M)[p] = a_;                                                      \
        }                                                                     \
        float acc_ = 0.0f;                                                    \
        _Pragma("unroll")                                                     \
        for (int k = 0; k < 8; k++) acc_ = fmaf(wsc_[k], cvec[k], acc_);      \
        const float n1_ = sm_n[(S)][i];                                       \
        (C) = acc_ * (jh ? inv_ * SQDT * n1_ : dti_);                         \
    } while (0)

    // one full step: chain matvec with (MC, CC), build (MN, CN) for t+1
#define STEP(T, RB, WB, MC, CC, MN, CN) do {                                  \
        /* ---- z-critical chain ---- */                                      \
        const ulonglong2* zsrc_ =                                             \
            reinterpret_cast<const ulonglong2*>(&sm_z[(RB)][16 * jh]);        \
        ulonglong2 z4_[4];                                                    \
        _Pragma("unroll")                                                     \
        for (int m = 0; m < 4; m++) z4_[m] = zsrc_[m];                        \
        ull ae_ = pack2((CC), 0.0f), ao_ = 0ull;                              \
        _Pragma("unroll")                                                     \
        for (int m = 0; m < 4; m++) {                                         \
            ae_ = ffma2((MC)[2 * m + 0], z4_[m].x, ae_);                      \
            ao_ = ffma2((MC)[2 * m + 1], z4_[m].y, ao_);                      \
        }                                                                     \
        const float2 sv_ = unpack2(ffma2(ae_, ONE2, ao_));                    \
        const float ph_ = sv_.x + sv_.y;                                      \
        const float zi_ = ph_ + __shfl_xor_sync(0xffffffffu, ph_, 1);         \
        /* ---- off-chain: prefetch + next-step M/c ---- */                   \
        if (h == 0) {                                                         \
            const int tp_ = (T) + PF;                                         \
            if (tp_ < NT) {                                                   \
                const int ps_ = tp_ & (RING - 1);                             \
                if (l < 8)                                                    \
                    cp16(s_n + (uint32_t)(ps_ * ND + l * 4) * 4,              \
                         gn + (size_t)tp_ * NB * ND + l * 4);                 \
                else if (l < 10)                                              \
                    cp16(s_w + (uint32_t)(ps_ * 8 + (l - 8) * 4) * 4,         \
                         gw + (size_t)tp_ * NB * NK + (l - 8) * 4);           \
            }                                                                 \
            asm volatile("cp.async.commit_group;" ::: "memory");              \
        }                                                                     \
        BUILD(((T) + 1) & (RING - 1), (MN), (CN));                            \
        /* ---- publish ---- */                                               \
        if (jh == 0) {                                                        \
            sm_z[(WB)][i] = zi_;                                              \
            yp[(size_t)(T) * NB * ND] = zi_;                                  \
        }                                                                     \
        if (h == 0)                                                           \
            asm volatile("cp.async.wait_group %0;" :: "n"(PF - 2) : "memory");\
        __syncthreads();                                                      \
    } while (0)

    // prologue: M/c for step 0 from ring slot 0
    ull Mc[8], Mn[8];
    float cC, cN;
    BUILD(0, Mc, cC);

    for (int t = 0; t < NT; t += 2) {
        STEP(t,     0, 1, Mc, cC, Mn, cN);
        STEP(t + 1, 1, 0, Mn, cN, Mc, cC);
    }
#undef STEP
#undef BUILD
}

extern "C" void kernel_launch(void* const* d_in, const int* in_sizes, int n_in,
                              void* d_out, int out_size) {
    const float* z0      = (const float*)d_in[0];
    const float* s_probs = (const float*)d_in[1];
    const float* noise   = (const float*)d_in[2];
    const float* A_s     = (const float*)d_in[3];
    const float* b_s     = (const float*)d_in[4];
    const float* Q_chol  = (const float*)d_in[5];
    float* ys = (float*)d_out;

    slds_scan_kernel<<<NB, 64>>>(z0, s_probs, noise, A_s, b_s, Q_chol, ys);
}

// round 11
// speedup vs baseline: 1.0011x; 1.0004x over previous
#include <cuda_runtime.h>
#include <cstdint>

#define NB 512
#define NT 2048
#define NK 8
#define ND 32
#define DTC 0.05f
#define SQDT 0.22360679774997896f  // sqrt(0.05)
#define PF 6                        // prefetch distance (steps)
#define RING 8                      // smem ring slots

typedef unsigned long long ull;

__device__ __forceinline__ ull ffma2(ull a, ull b, ull c) {
    ull d;
    asm("fma.rn.f32x2 %0, %1, %2, %3;" : "=l"(d) : "l"(a), "l"(b), "l"(c));
    return d;
}
__device__ __forceinline__ float2 unpack2(ull v) {
    float2 r;
    asm("mov.b64 {%0, %1}, %2;" : "=f"(r.x), "=f"(r.y) : "l"(v));
    return r;
}
__device__ __forceinline__ ull pack2(float lo, float hi) {
    ull v;
    asm("mov.b64 %0, {%1, %2};" : "=l"(v) : "f"(lo), "f"(hi));
    return v;
}
__device__ __forceinline__ void cp16(uint32_t saddr, const void* gaddr) {
    asm volatile("cp.async.ca.shared.global [%0], [%1], 16;"
                 :: "r"(saddr), "l"(gaddr) : "memory");
}

__global__ void __launch_bounds__(64, 1)
slds_scan_kernel(const float* __restrict__ z0,
                 const float* __restrict__ s_probs,  // [T,B,K]
                 const float* __restrict__ noise,    // [T,B,D]
                 const float* __restrict__ A_s,      // [K,D,D]
                 const float* __restrict__ b_s,      // [K,D]
                 const float* __restrict__ Q_chol,   // [K,D]
                 float* __restrict__ ys)             // [T,B,D]
{
    __shared__ __align__(16) float sm_w[RING][8];
    __shared__ __align__(16) float sm_n[RING][ND];
    __shared__ __align__(16) float sm_z[2][ND];      // double-buffered state

    const int l  = threadIdx.x & 31;   // lane
    const int h  = threadIdx.x >> 5;   // warp: dims [16h, 16h+16)
    const int i  = 16 * h + (l >> 1);  // owned output dim
    const int jh = l & 1;              // j-half: columns [16jh, 16jh+16)
    const int b  = blockIdx.x;

    const ull ONE2 = pack2(1.0f, 1.0f);

    // ---- A rows (all 8 k, this lane's j-half) as 8 f32x2 pairs each ----
    ull A2[NK][8];
#pragma unroll
    for (int k = 0; k < NK; k++) {
        const ulonglong2* row = reinterpret_cast<const ulonglong2*>(
            A_s + ((size_t)k * ND + i) * ND + 16 * jh);
#pragma unroll
        for (int m = 0; m < 4; m++) {
            ulonglong2 v = row[m];
            A2[k][2 * m + 0] = v.x;
            A2[k][2 * m + 1] = v.y;
        }
    }
    // identity mask: 1.0 in the packed slot holding column j == i (if owned)
    ull dmask8[8];
#pragma unroll
    for (int p = 0; p < 8; p++) {
        const bool owned = ((i >> 4) == jh) && (((i & 15) >> 1) == p);
        dmask8[p] = owned ? pack2((i & 1) == 0 ? 1.0f : 0.0f,
                                  (i & 1) == 1 ? 1.0f : 0.0f)
                          : 0ull;
    }
    // c-vector: even lanes carry drift bias, odd lanes carry diffusion diag
    float cvec[NK];
#pragma unroll
    for (int k = 0; k < NK; k++)
        cvec[k] = (jh == 0) ? b_s[k * ND + i] : Q_chol[k * ND + i];

    // ---- cp.async ring (warp 0 issues) ----
    const uint32_t s_n = (uint32_t)__cvta_generic_to_shared(&sm_n[0][0]);
    const uint32_t s_w = (uint32_t)__cvta_generic_to_shared(&sm_w[0][0]);
    const float* gn = noise   + (size_t)b * ND;
    const float* gw = s_probs + (size_t)b * NK;

    if (h == 0) {
#pragma unroll
        for (int s = 0; s < PF; s++) {
            if (l < 8)
                cp16(s_n + (uint32_t)(s * ND + l * 4) * 4,
                     gn + (size_t)s * NB * ND + l * 4);
            else if (l < 10)
                cp16(s_w + (uint32_t)(s * 8 + (l - 8) * 4) * 4,
                     gw + (size_t)s * NB * NK + (l - 8) * 4);
            asm volatile("cp.async.commit_group;" ::: "memory");
        }
        // guarantee slots 0 AND 1 complete (we read slot t+1 during step t)
        asm volatile("cp.async.wait_group %0;" :: "n"(PF - 2) : "memory");
    }

    // ---- initial state into buffer 0 ----
    if (jh == 0) sm_z[0][i] = z0[(size_t)b * ND + i];
    __syncthreads();   // publishes ring slots 0..1 + sm_z[0]

    float* yp = ys + (size_t)b * ND + i;

    // build M_slot/c_slot from ring slot S (off-chain work)
#define BUILD(S, M, C) do {                                                   \
        const float4 wa_ = *reinterpret_cast<const float4*>(&sm_w[(S)][0]);   \
        const float4 wb_ = *reinterpret_cast<const float4*>(&sm_w[(S)][4]);   \
        const float wsum_ = ((wa_.x + wa_.y) + (wa_.z + wa_.w)) +             \
                            ((wb_.x + wb_.y) + (wb_.z + wb_.w));              \
        const float inv_ = __fdividef(1.0f, wsum_);                           \
        const float dti_ = DTC * inv_;                                        \
        const float wsc_[8] = { wa_.x, wa_.y, wa_.z, wa_.w,                   \
                                wb_.x, wb_.y, wb_.z, wb_.w };                 \
        ull wt_[8];                                                           \
        _Pragma("unroll")                                                     \
        for (int k = 0; k < 8; k++) {                                         \
            const float s_ = dti_ * wsc_[k];                                  \
            wt_[k] = pack2(s_, s_);                                           \
        }                                                                     \
        _Pragma("unroll")                                                     \
        for (int p = 0; p < 8; p++) {                                         \
            ull a_ = dmask8[p];                                               \
            _Pragma("unroll")                                                 \
            for (int k = 0; k < 8; k++) a_ = ffma2(wt_[k], A2[k][p], a_);     \
            (M)[p] = a_;                                                      \
        }                                                                     \
        float acc_ = 0.0f;                                                    \
        _Pragma("unroll")                                                     \
        for (int k = 0; k < 8; k++) acc_ = fmaf(wsc_[k], cvec[k], acc_);      \
        const float n1_ = sm_n[(S)][i];                                       \
        (C) = acc_ * (jh ? inv_ * SQDT * n1_ : dti_);                         \
    } while (0)

    // one full step: chain matvec with (MC, CC), build (MN, CN) for t+1
#define STEP(T, RB, WB, MC, CC, MN, CN) do {                                  \
        /* ---- z-critical chain ---- */                                      \
        const ulonglong2* zsrc_ =                                             \
            reinterpret_cast<const ulonglong2*>(&sm_z[(RB)][16 * jh]);        \
        ulonglong2 z4_[4];                                                    \
        _Pragma("unroll")                                                     \
        for (int m = 0; m < 4; m++) z4_[m] = zsrc_[m];                        \
        ull ae_ = pack2((CC), 0.0f), ao_ = 0ull;                              \
        _Pragma("unroll")                                                     \
        for (int m = 0; m < 4; m++) {                                         \
            ae_ = ffma2((MC)[2 * m + 0], z4_[m].x, ae_);                      \
            ao_ = ffma2((MC)[2 * m + 1], z4_[m].y, ao_);                      \
        }                                                                     \
        const float2 sv_ = unpack2(ffma2(ae_, ONE2, ao_));                    \
        const float ph_ = sv_.x + sv_.y;                                      \
        const float zi_ = ph_ + __shfl_xor_sync(0xffffffffu, ph_, 1);         \
        /* ---- off-chain: prefetch + next-step M/c ---- */                   \
        if (h == 0) {                                                         \
            const int tp_ = (T) + PF;                                         \
            if (tp_ < NT) {                                                   \
                const int ps_ = tp_ & (RING - 1);                             \
                if (l < 8)                                                    \
                    cp16(s_n + (uint32_t)(ps_ * ND + l * 4) * 4,              \
                         gn + (size_t)tp_ * NB * ND + l * 4);                 \
                else if (l < 10)                                              \
                    cp16(s_w + (uint32_t)(ps_ * 8 + (l - 8) * 4) * 4,         \
                         gw + (size_t)tp_ * NB * NK + (l - 8) * 4);           \
            }                                                                 \
            asm volatile("cp.async.commit_group;" ::: "memory");              \
        }                                                                     \
        BUILD(((T) + 1) & (RING - 1), (MN), (CN));                            \
        /* ---- publish ---- */                                               \
        if (jh == 0) {                                                        \
            sm_z[(WB)][i] = zi_;                                              \
            yp[(size_t)(T) * NB * ND] = zi_;                                  \
        }                                                                     \
        if (h == 0)                                                           \
            asm volatile("cp.async.wait_group %0;" :: "n"(PF - 2) : "memory");\
        __syncthreads();                                                      \
    } while (0)

    // prologue: M/c for step 0 from ring slot 0
    ull Mc[8], Mn[8];
    float cC, cN;
    BUILD(0, Mc, cC);

    for (int t = 0; t < NT; t += 2) {
        STEP(t,     0, 1, Mc, cC, Mn, cN);
        STEP(t + 1, 1, 0, Mn, cN, Mc, cC);
    }
#undef STEP
#undef BUILD
}

extern "C" void kernel_launch(void* const* d_in, const int* in_sizes, int n_in,
                              void* d_out, int out_size) {
    const float* z0      = (const float*)d_in[0];
    const float* s_probs = (const float*)d_in[1];
    const float* noise   = (const float*)d_in[2];
    const float* A_s     = (const float*)d_in[3];
    const float* b_s     = (const float*)d_in[4];
    const float* Q_chol  = (const float*)d_in[5];
    float* ys = (float*)d_out;

    slds_scan_kernel<<<NB, 64>>>(z0, s_probs, noise, A_s, b_s, Q_chol, ys);
}

// round 13
// speedup vs baseline: 1.0015x; 1.0004x over previous
#include <cuda_runtime.h>
#include <cstdint>

#define NB 512
#define NT 2048
#define NK 8
#define ND 32
#define DTC 0.05f
#define SQDT 0.22360679774997896f  // sqrt(0.05)
#define PF 6                        // prefetch distance (steps)
#define RING 8                      // smem ring slots

typedef unsigned long long ull;

__device__ __forceinline__ ull ffma2(ull a, ull b, ull c) {
    ull d;
    asm("fma.rn.f32x2 %0, %1, %2, %3;" : "=l"(d) : "l"(a), "l"(b), "l"(c));
    return d;
}
__device__ __forceinline__ float2 unpack2(ull v) {
    float2 r;
    asm("mov.b64 {%0, %1}, %2;" : "=f"(r.x), "=f"(r.y) : "l"(v));
    return r;
}
__device__ __forceinline__ ull pack2(float lo, float hi) {
    ull v;
    asm("mov.b64 %0, {%1, %2};" : "=l"(v) : "f"(lo), "f"(hi));
    return v;
}
__device__ __forceinline__ void cp16(uint32_t saddr, const void* gaddr) {
    asm volatile("cp.async.ca.shared.global [%0], [%1], 16;"
                 :: "r"(saddr), "l"(gaddr) : "memory");
}

__global__ void __launch_bounds__(64, 1)
slds_scan_kernel(const float* __restrict__ z0,
                 const float* __restrict__ s_probs,  // [T,B,K]
                 const float* __restrict__ noise,    // [T,B,D]
                 const float* __restrict__ A_s,      // [K,D,D]
                 const float* __restrict__ b_s,      // [K,D]
                 const float* __restrict__ Q_chol,   // [K,D]
                 float* __restrict__ ys)             // [T,B,D]
{
    __shared__ __align__(16) float sm_w[RING][8];
    __shared__ __align__(16) float sm_n[RING][ND];
    __shared__ __align__(16) float sm_z[2][ND];      // double-buffered state

    const int l  = threadIdx.x & 31;   // lane
    const int h  = threadIdx.x >> 5;   // warp: dims [16h, 16h+16)
    const int i  = 16 * h + (l >> 1);  // owned output dim
    const int jh = l & 1;              // j-half: columns [16jh, 16jh+16)
    const int b  = blockIdx.x;

    const ull ONE2 = pack2(1.0f, 1.0f);

    // ---- A rows (all 8 k, this lane's j-half) as 8 f32x2 pairs each ----
    ull A2[NK][8];
#pragma unroll
    for (int k = 0; k < NK; k++) {
        const ulonglong2* row = reinterpret_cast<const ulonglong2*>(
            A_s + ((size_t)k * ND + i) * ND + 16 * jh);
#pragma unroll
        for (int m = 0; m < 4; m++) {
            ulonglong2 v = row[m];
            A2[k][2 * m + 0] = v.x;
            A2[k][2 * m + 1] = v.y;
        }
    }
    // identity mask: 1.0 in the packed slot holding column j == i (if owned)
    ull dmask8[8];
#pragma unroll
    for (int p = 0; p < 8; p++) {
        const bool owned = ((i >> 4) == jh) && (((i & 15) >> 1) == p);
        dmask8[p] = owned ? pack2((i & 1) == 0 ? 1.0f : 0.0f,
                                  (i & 1) == 1 ? 1.0f : 0.0f)
                          : 0ull;
    }
    // c-vector: even lanes carry drift bias, odd lanes carry diffusion diag
    float cvec[NK];
#pragma unroll
    for (int k = 0; k < NK; k++)
        cvec[k] = (jh == 0) ? b_s[k * ND + i] : Q_chol[k * ND + i];

    // ---- cp.async ring (warp 0 issues) ----
    const uint32_t s_n = (uint32_t)__cvta_generic_to_shared(&sm_n[0][0]);
    const uint32_t s_w = (uint32_t)__cvta_generic_to_shared(&sm_w[0][0]);
    const float* gn = noise   + (size_t)b * ND;
    const float* gw = s_probs + (size_t)b * NK;

    if (h == 0) {
#pragma unroll
        for (int s = 0; s < PF; s++) {
            if (l < 8)
                cp16(s_n + (uint32_t)(s * ND + l * 4) * 4,
                     gn + (size_t)s * NB * ND + l * 4);
            else if (l < 10)
                cp16(s_w + (uint32_t)(s * 8 + (l - 8) * 4) * 4,
                     gw + (size_t)s * NB * NK + (l - 8) * 4);
            asm volatile("cp.async.commit_group;" ::: "memory");
        }
        // guarantee slots 0 AND 1 complete (we read slot t+1 during step t)
        asm volatile("cp.async.wait_group %0;" :: "n"(PF - 2) : "memory");
    }

    // ---- initial state into buffer 0 ----
    if (jh == 0) sm_z[0][i] = z0[(size_t)b * ND + i];
    __syncthreads();   // publishes ring slots 0..1 + sm_z[0]

    float* yp = ys + (size_t)b * ND + i;

    // build M_slot/c_slot from ring slot S (off-chain work)
#define BUILD(S, M, C) do {                                                   \
        const float4 wa_ = *reinterpret_cast<const float4*>(&sm_w[(S)][0]);   \
        const float4 wb_ = *reinterpret_cast<const float4*>(&sm_w[(S)][4]);   \
        const float wsum_ = ((wa_.x + wa_.y) + (wa_.z + wa_.w)) +             \
                            ((wb_.x + wb_.y) + (wb_.z + wb_.w));              \
        const float inv_ = __fdividef(1.0f, wsum_);                           \
        const float dti_ = DTC * inv_;                                        \
        const float wsc_[8] = { wa_.x, wa_.y, wa_.z, wa_.w,                   \
                                wb_.x, wb_.y, wb_.z, wb_.w };                 \
        ull wt_[8];                                                           \
        _Pragma("unroll")                                                     \
        for (int k = 0; k < 8; k++) {                                         \
            const float s_ = dti_ * wsc_[k];                                  \
            wt_[k] = pack2(s_, s_);                                           \
        }                                                                     \
        _Pragma("unroll")                                                     \
        for (int p = 0; p < 8; p++) {                                         \
            ull a_ = dmask8[p];                                               \
            _Pragma("unroll")                                                 \
            for (int k = 0; k < 8; k++) a_ = ffma2(wt_[k], A2[k][p], a_);     \
            (M)[p] = a_;                                                      \
        }                                                                     \
        float acc_ = 0.0f;                                                    \
        _Pragma("unroll")                                                     \
        for (int k = 0; k < 8; k++) acc_ = fmaf(wsc_[k], cvec[k], acc_);      \
        const float n1_ = sm_n[(S)][i];                                       \
        (C) = acc_ * (jh ? inv_ * SQDT * n1_ : dti_);                         \
    } while (0)

    // one full step: chain matvec with (MC, CC), build (MN, CN) for t+1
#define STEP(T, RB, WB, MC, CC, MN, CN) do {                                  \
        /* ---- z-critical chain ---- */                                      \
        const ulonglong2* zsrc_ =                                             \
            reinterpret_cast<const ulonglong2*>(&sm_z[(RB)][16 * jh]);        \
        ulonglong2 z4_[4];                                                    \
        _Pragma("unroll")                                                     \
        for (int m = 0; m < 4; m++) z4_[m] = zsrc_[m];                        \
        ull ae_ = pack2((CC), 0.0f), ao_ = 0ull;                              \
        _Pragma("unroll")                                                     \
        for (int m = 0; m < 4; m++) {                                         \
            ae_ = ffma2((MC)[2 * m + 0], z4_[m].x, ae_);                      \
            ao_ = ffma2((MC)[2 * m + 1], z4_[m].y, ao_);                      \
        }                                                                     \
        const float2 sv_ = unpack2(ffma2(ae_, ONE2, ao_));                    \
        const float ph_ = sv_.x + sv_.y;                                      \
        const float zi_ = ph_ + __shfl_xor_sync(0xffffffffu, ph_, 1);         \
        /* ---- off-chain: prefetch + next-step M/c ---- */                   \
        if (h == 0) {                                                         \
            const int tp_ = (T) + PF;                                         \
            if (tp_ < NT) {                                                   \
                const int ps_ = tp_ & (RING - 1);                             \
                if (l < 8)                                                    \
                    cp16(s_n + (uint32_t)(ps_ * ND + l * 4) * 4,              \
                         gn + (size_t)tp_ * NB * ND + l * 4);                 \
                else if (l < 10)                                              \
                    cp16(s_w + (uint32_t)(ps_ * 8 + (l - 8) * 4) * 4,         \
                         gw + (size_t)tp_ * NB * NK + (l - 8) * 4);           \
            }                                                                 \
            asm volatile("cp.async.commit_group;" ::: "memory");              \
        }                                                                     \
        BUILD(((T) + 1) & (RING - 1), (MN), (CN));                            \
        /* ---- publish ---- */                                               \
        if (jh == 0) {                                                        \
            sm_z[(WB)][i] = zi_;                                              \
            yp[(size_t)(T) * NB * ND] = zi_;                                  \
        }                                                                     \
        if (h == 0)                                                           \
            asm volatile("cp.async.wait_group %0;" :: "n"(PF - 2) : "memory");\
        __syncthreads();                                                      \
    } while (0)

    // prologue: M/c for step 0 from ring slot 0
    ull Mc[8], Mn[8];
    float cC, cN;
    BUILD(0, Mc, cC);

    for (int t = 0; t < NT; t += 2) {
        STEP(t,     0, 1, Mc, cC, Mn, cN);
        STEP(t + 1, 1, 0, Mn, cN, Mc, cC);
    }
#undef STEP
#undef BUILD
}

extern "C" void kernel_launch(void* const* d_in, const int* in_sizes, int n_in,
                              void* d_out, int out_size) {
    const float* z0      = (const float*)d_in[0];
    const float* s_probs = (const float*)d_in[1];
    const float* noise   = (const float*)d_in[2];
    const float* A_s     = (const float*)d_in[3];
    const float* b_s     = (const float*)d_in[4];
    const float* Q_chol  = (const float*)d_in[5];
    float* ys = (float*)d_out;

    slds_scan_kernel<<<NB, 64>>>(z0, s_probs, noise, A_s, b_s, Q_chol, ys);
}